// round 9
// baseline (speedup 1.0000x reference)
#include <cuda_runtime.h>
#include <cuda_fp16.h>
#include <cstdint>
#include <math.h>

// ---------------- problem constants ----------------
#define BATCH    16384
#define F_IN     768
#define F_OUT    512
#define BM       64            // batch rows per CTA
#define BK       64            // K chunk
#define NCHUNK   (F_IN / BK)   // 12 chunks per pass
#define NPASS    2
#define TOTCHUNK (NCHUNK * NPASS)  // 24
#define NTHREADS 256
#define CTAS     (BATCH / BM)  // 256

// ---------------- smem layout (bytes) ----------------
// A resident: 12 chunk-blocks x (64 rows x 128B) = 98304
// B double buffer: 2 x (512 rows x 128B) = 131072
#define SM_A     0
#define SM_B     98304
#define SM_TOTAL (SM_B + 2 * 65536)    // 229376 (fits 227KB max block smem)

// ---------------- helpers ----------------
__device__ __forceinline__ uint32_t smem_u32(const void* p) {
    uint32_t a;
    asm("{ .reg .u64 t; cvta.to.shared.u64 t, %1; cvt.u32.u64 %0, t; }" : "=r"(a) : "l"(p));
    return a;
}

#define LDSM_X4(r0, r1, r2, r3, addr) \
    asm volatile("ldmatrix.sync.aligned.m8n8.x4.shared.b16 {%0,%1,%2,%3}, [%4];" \
                 : "=r"(r0), "=r"(r1), "=r"(r2), "=r"(r3) : "r"(addr))

// fp16-accumulate MMA: D,C are 2 x b32 (4 halves)
#define MMA16816H(d, a, b) \
    asm volatile("mma.sync.aligned.m16n8k16.row.col.f16.f16.f16.f16 " \
                 "{%0,%1}, {%2,%3,%4,%5}, {%6,%7}, {%0,%1};" \
                 : "+r"((d)[0]), "+r"((d)[1]) \
                 : "r"((a)[0]), "r"((a)[1]), "r"((a)[2]), "r"((a)[3]), \
                   "r"((b)[0]), "r"((b)[1]))

#define CP_ASYNC16(dst, src) \
    asm volatile("cp.async.cg.shared.global [%0], [%1], 16;" :: "r"(dst), "l"(src) : "memory")
#define CP_COMMIT() asm volatile("cp.async.commit_group;" ::: "memory")
#define CP_WAIT0()  asm volatile("cp.async.wait_group 0;" ::: "memory")

// cvt 8 f32 -> 8 f16, one swizzled 16B STS
__device__ __forceinline__ void sts_a16(uint32_t addr, float4 v0, float4 v1) {
    uint32_t u0, u1, u2, u3;
    asm("cvt.rn.f16x2.f32 %0, %1, %2;" : "=r"(u0) : "f"(v0.y), "f"(v0.x));
    asm("cvt.rn.f16x2.f32 %0, %1, %2;" : "=r"(u1) : "f"(v0.w), "f"(v0.z));
    asm("cvt.rn.f16x2.f32 %0, %1, %2;" : "=r"(u2) : "f"(v1.y), "f"(v1.x));
    asm("cvt.rn.f16x2.f32 %0, %1, %2;" : "=r"(u3) : "f"(v1.w), "f"(v1.z));
    asm volatile("st.shared.v4.u32 [%0], {%1,%2,%3,%4};"
                 :: "r"(addr), "r"(u0), "r"(u1), "r"(u2), "r"(u3) : "memory");
}

// ---------------- W1 fp32 -> fp16 pre-conversion ----------------
__device__ __align__(16) __half g_W1h[F_OUT * F_IN];

__global__ void convert_w1_kernel(const float* __restrict__ W1) {
    int i = blockIdx.x * blockDim.x + threadIdx.x;
    const int n = F_OUT * F_IN / 4;
    if (i < n) {
        float4 v = reinterpret_cast<const float4*>(W1)[i];
        reinterpret_cast<__half2*>(g_W1h)[i * 2]     = __floats2half2_rn(v.x, v.y);
        reinterpret_cast<__half2*>(g_W1h)[i * 2 + 1] = __floats2half2_rn(v.z, v.w);
    }
}

// ---------------- fused perspective-network kernel ----------------
// 8 warps, 64x64 warp tiles (warpN = wid). A resident in smem for whole pass.
// MMA accumulates in fp16; flushed to fp32 running sums every K=64 chunk.
__global__ void __launch_bounds__(NTHREADS, 1)
persp_kernel(const float* __restrict__ stm, const float* __restrict__ nstm,
             const float* __restrict__ b1, const float* __restrict__ W2,
             const float* __restrict__ b2, float* __restrict__ out) {
    extern __shared__ __align__(1024) char smem[];
    const uint32_t sb = smem_u32(smem);
    const int tid   = threadIdx.x;
    const int lane  = tid & 31;
    const int warpN = tid >> 5;    // 0..7
    const int m0 = blockIdx.x * BM;

    // ---- ldmatrix per-lane geometry ----
    const uint32_t aInOff = (uint32_t)(((lane >> 3) & 1) * 8 + (lane & 7)) * 128;
    const uint32_t aXor   = ((uint32_t)(lane >> 4) * 16) ^ ((uint32_t)(lane & 7) << 4);
    const uint32_t bInOff = (uint32_t)(warpN * 64 + ((lane >> 4) & 1) * 8 + (lane & 7)) * 128;
    const uint32_t bXor   = (((uint32_t)(lane >> 3) & 1) * 16) ^ ((uint32_t)(lane & 7) << 4);

    // ---- fill geometry ----
    // A: 64 rows x 64 f32 per chunk; thread -> row tid>>2, 16 floats at (tid&3)*16
    const int aRowG = tid >> 2;
    const int aSeg  = tid & 3;
    const uint32_t aSts0 = aRowG * 128 + (((uint32_t)aSeg * 32)      ^ ((uint32_t)(aRowG & 7) << 4));
    const uint32_t aSts1 = aRowG * 128 + (((uint32_t)aSeg * 32 + 16) ^ ((uint32_t)(aRowG & 7) << 4));
    // B: 512 rows x 64 f16; thread -> rows (tid>>3)+32j (j<16), 16B seg tid&7
    const int bRow0 = tid >> 3;
    const int bSeg  = tid & 7;
    const uint32_t bDstBase = bRow0 * 128 + (((uint32_t)bSeg * 16) ^ ((uint32_t)(bRow0 & 7) << 4));
    const __half* bSrcBase = g_W1h + (size_t)bRow0 * F_IN + bSeg * 8;

    float    facc[4][8][4] = {};
    uint32_t hacc[4][8][2] = {};
    float rowsum[8] = {0.f, 0.f, 0.f, 0.f, 0.f, 0.f, 0.f, 0.f};

    // ---- prologue: B chunk 0 via cp.async; A pass-0 resident fill ----
    {
#pragma unroll
        for (int j = 0; j < 16; ++j)
            CP_ASYNC16(sb + SM_B + bDstBase + j * 4096, bSrcBase + (size_t)j * 32 * F_IN);
        CP_COMMIT();
        const float* Xr = stm + (size_t)(m0 + aRowG) * F_IN + aSeg * 16;
#pragma unroll
        for (int c = 0; c < NCHUNK; ++c) {
            const float4* s = reinterpret_cast<const float4*>(Xr + c * BK);
            float4 v0 = s[0], v1 = s[1], v2 = s[2], v3 = s[3];
            sts_a16(sb + SM_A + c * 8192 + aSts0, v0, v1);
            sts_a16(sb + SM_A + c * 8192 + aSts1, v2, v3);
        }
        CP_WAIT0();
        __syncthreads();
    }

    for (int g = 0; g < TOTCHUNK; ++g) {
        const int p = g & 1;
        const uint32_t bufA = sb + SM_A + (g % NCHUNK) * 8192;
        const uint32_t bufB = sb + SM_B + p * 65536;

        // prefetch B for chunk g+1 into the other stage
        if (g + 1 < TOTCHUNK) {
            const int c1 = (g + 1) % NCHUNK;
            const __half* src = bSrcBase + c1 * BK;
            const uint32_t dst = sb + SM_B + (p ^ 1) * 65536 + bDstBase;
#pragma unroll
            for (int j = 0; j < 16; ++j)
                CP_ASYNC16(dst + j * 4096, src + (size_t)j * 32 * F_IN);
            CP_COMMIT();
        }

        // ---- compute chunk g (fp16 accumulate) ----
#pragma unroll
        for (int ks = 0; ks < 4; ++ks) {
            const uint32_t kx = (uint32_t)(ks << 5);
            uint32_t aa[4][4];
#pragma unroll
            for (int mt = 0; mt < 4; ++mt)
                LDSM_X4(aa[mt][0], aa[mt][1], aa[mt][2], aa[mt][3],
                        bufA + mt * 2048 + aInOff + (aXor ^ kx));
            uint32_t bb[8][2];
#pragma unroll
            for (int nt2 = 0; nt2 < 4; ++nt2) {
                uint32_t r0, r1, r2, r3;
                LDSM_X4(r0, r1, r2, r3, bufB + bInOff + nt2 * 2048 + (bXor ^ kx));
                bb[nt2 * 2][0] = r0;     bb[nt2 * 2][1] = r1;
                bb[nt2 * 2 + 1][0] = r2; bb[nt2 * 2 + 1][1] = r3;
            }
#pragma unroll
            for (int mt = 0; mt < 4; ++mt)
#pragma unroll
                for (int nt = 0; nt < 8; ++nt)
                    MMA16816H(hacc[mt][nt], aa[mt], bb[nt]);
        }

        // ---- flush fp16 chunk accumulators into fp32 running sums ----
#pragma unroll
        for (int mt = 0; mt < 4; ++mt)
#pragma unroll
            for (int nt = 0; nt < 8; ++nt) {
                float2 f0 = __half22float2(*reinterpret_cast<__half2*>(&hacc[mt][nt][0]));
                float2 f1 = __half22float2(*reinterpret_cast<__half2*>(&hacc[mt][nt][1]));
                facc[mt][nt][0] += f0.x; facc[mt][nt][1] += f0.y;
                facc[mt][nt][2] += f1.x; facc[mt][nt][3] += f1.y;
                hacc[mt][nt][0] = 0u;    hacc[mt][nt][1] = 0u;
            }

        // ---- end-of-pass: bias + clip + W2 partial dot, reset facc ----
        if (g == NCHUNK - 1 || g == TOTCHUNK - 1) {
            const int w2o = (g >= NCHUNK) ? F_OUT : 0;
#pragma unroll
            for (int mt = 0; mt < 4; ++mt) {
#pragma unroll
                for (int nt = 0; nt < 8; ++nt) {
                    const int nb = warpN * 64 + nt * 8 + (lane & 3) * 2;
                    const float2 bv = __ldg(reinterpret_cast<const float2*>(b1 + nb));
                    const float2 wv = __ldg(reinterpret_cast<const float2*>(W2 + w2o + nb));
                    float h;
                    h = fminf(fmaxf(facc[mt][nt][0] + bv.x, 0.f), 1.f); rowsum[mt*2+0] = fmaf(h, wv.x, rowsum[mt*2+0]);
                    h = fminf(fmaxf(facc[mt][nt][1] + bv.y, 0.f), 1.f); rowsum[mt*2+0] = fmaf(h, wv.y, rowsum[mt*2+0]);
                    h = fminf(fmaxf(facc[mt][nt][2] + bv.x, 0.f), 1.f); rowsum[mt*2+1] = fmaf(h, wv.x, rowsum[mt*2+1]);
                    h = fminf(fmaxf(facc[mt][nt][3] + bv.y, 0.f), 1.f); rowsum[mt*2+1] = fmaf(h, wv.y, rowsum[mt*2+1]);
                    facc[mt][nt][0] = 0.f; facc[mt][nt][1] = 0.f;
                    facc[mt][nt][2] = 0.f; facc[mt][nt][3] = 0.f;
                }
            }
        }

        // ---- pass boundary: rebuild resident A from nstm ----
        if (g == NCHUNK - 1) {
            __syncthreads();   // everyone done reading pass-0 A
            const float* Xr = nstm + (size_t)(m0 + aRowG) * F_IN + aSeg * 16;
#pragma unroll
            for (int c = 0; c < NCHUNK; ++c) {
                const float4* s = reinterpret_cast<const float4*>(Xr + c * BK);
                float4 v0 = s[0], v1 = s[1], v2 = s[2], v3 = s[3];
                sts_a16(sb + SM_A + c * 8192 + aSts0, v0, v1);
                sts_a16(sb + SM_A + c * 8192 + aSts1, v2, v3);
            }
        }

        CP_WAIT0();
        __syncthreads();
    }

    // ---- cross-lane + cross-warp reduce, sigmoid, store ----
    float* red_s = reinterpret_cast<float*>(smem + SM_B);  // B buffers dead now
    if (tid < BM) red_s[tid] = 0.0f;
    __syncthreads();
#pragma unroll
    for (int r = 0; r < 8; ++r) {
        float v = rowsum[r];
        v += __shfl_xor_sync(0xFFFFFFFFu, v, 1);
        v += __shfl_xor_sync(0xFFFFFFFFu, v, 2);
        if ((lane & 3) == 0) {
            const int row = (r >> 1) * 16 + (r & 1) * 8 + (lane >> 2);
            atomicAdd(&red_s[row], v);
        }
    }
    __syncthreads();
    if (tid < BM) {
        const float z = red_s[tid] + __ldg(b2);
        out[m0 + tid] = 1.0f / (1.0f + expf(-z));
    }
}

// ---------------- launch ----------------
extern "C" void kernel_launch(void* const* d_in, const int* in_sizes, int n_in,
                              void* d_out, int out_size) {
    const float* stm  = (const float*)d_in[0];
    const float* nstm = (const float*)d_in[1];
    const float* W1   = (const float*)d_in[2];
    const float* b1   = (const float*)d_in[3];
    const float* W2   = (const float*)d_in[4];
    const float* b2   = (const float*)d_in[5];
    float* out = (float*)d_out;

    cudaFuncSetAttribute(persp_kernel, cudaFuncAttributeMaxDynamicSharedMemorySize, SM_TOTAL);

    const int nconv = F_OUT * F_IN / 4;
    convert_w1_kernel<<<(nconv + 255) / 256, 256>>>(W1);
    persp_kernel<<<CTAS, NTHREADS, SM_TOTAL>>>(stm, nstm, b1, W2, b2, out);
}

// round 11
// speedup vs baseline: 1.3276x; 1.3276x over previous
#include <cuda_runtime.h>
#include <cuda_fp16.h>
#include <cstdint>
#include <math.h>

// ---------------- problem constants ----------------
#define BATCH    16384
#define F_IN     768
#define F_OUT    512
#define BM       64
#define BK       64
#define NCHUNK   (F_IN / BK)        // 12
#define TOTCHUNK (NCHUNK * 2)       // 24
#define NTHREADS 320                // 8 consumer warps + 2 producer warps
#define CTAS     (BATCH / BM)       // 256

// ---------------- smem layout (bytes) ----------------
#define SM_RED   0                         // 64 f32
#define SM_A0    4096                      // 2 x 8192
#define SM_B     20480                     // 2 x 65536
#define SM_TOTAL (SM_B + 2 * 65536)        // 151552

// ---------------- helpers ----------------
__device__ __forceinline__ uint32_t smem_u32(const void* p) {
    uint32_t a;
    asm("{ .reg .u64 t; cvta.to.shared.u64 t, %1; cvt.u32.u64 %0, t; }" : "=r"(a) : "l"(p));
    return a;
}

#define LDSM_X4(r0, r1, r2, r3, addr) \
    asm volatile("ldmatrix.sync.aligned.m8n8.x4.shared.b16 {%0,%1,%2,%3}, [%4];" \
                 : "=r"(r0), "=r"(r1), "=r"(r2), "=r"(r3) : "r"(addr))

#define MMA16816(d, a, b) \
    asm volatile("mma.sync.aligned.m16n8k16.row.col.f32.f16.f16.f32 " \
                 "{%0,%1,%2,%3}, {%4,%5,%6,%7}, {%8,%9}, {%0,%1,%2,%3};" \
                 : "+f"((d)[0]), "+f"((d)[1]), "+f"((d)[2]), "+f"((d)[3]) \
                 : "r"((a)[0]), "r"((a)[1]), "r"((a)[2]), "r"((a)[3]), \
                   "r"((b)[0]), "r"((b)[1]))

#define CP_ASYNC16(dst, src) \
    asm volatile("cp.async.cg.shared.global [%0], [%1], 16;" :: "r"(dst), "l"(src) : "memory")
#define CP_COMMIT() asm volatile("cp.async.commit_group;" ::: "memory")
#define CP_WAIT0()  asm volatile("cp.async.wait_group 0;" ::: "memory")

__device__ __forceinline__ void sts_a16(uint32_t addr, float4 v0, float4 v1) {
    uint32_t u0, u1, u2, u3;
    asm("cvt.rn.f16x2.f32 %0, %1, %2;" : "=r"(u0) : "f"(v0.y), "f"(v0.x));
    asm("cvt.rn.f16x2.f32 %0, %1, %2;" : "=r"(u1) : "f"(v0.w), "f"(v0.z));
    asm("cvt.rn.f16x2.f32 %0, %1, %2;" : "=r"(u2) : "f"(v1.y), "f"(v1.x));
    asm("cvt.rn.f16x2.f32 %0, %1, %2;" : "=r"(u3) : "f"(v1.w), "f"(v1.z));
    asm volatile("st.shared.v4.u32 [%0], {%1,%2,%3,%4};"
                 :: "r"(addr), "r"(u0), "r"(u1), "r"(u2), "r"(u3) : "memory");
}

// ---------------- W1 fp32 -> fp16 pre-conversion ----------------
__device__ __align__(16) __half g_W1h[F_OUT * F_IN];

__global__ void __launch_bounds__(512) convert_w1_kernel(const float* __restrict__ W1) {
    int i = blockIdx.x * blockDim.x + threadIdx.x;
    const int n = F_OUT * F_IN / 4;
    if (i < n) {
        float4 v = reinterpret_cast<const float4*>(W1)[i];
        reinterpret_cast<__half2*>(g_W1h)[i * 2]     = __floats2half2_rn(v.x, v.y);
        reinterpret_cast<__half2*>(g_W1h)[i * 2 + 1] = __floats2half2_rn(v.z, v.w);
    }
}

// ---------------- fused perspective-network kernel (warp-specialized) ----------------
// wid 0..7: consumers, 64x64 output tiles (warpN = wid), ONLY ldmatrix+mma+epilogue.
// wid 8..9: producers, fill A (LDG f32 -> cvt -> swizzled STS, FULL 64-col rows)
//           and B (cp.async).
__global__ void __launch_bounds__(NTHREADS, 1)
persp_kernel(const float* __restrict__ stm, const float* __restrict__ nstm,
             const float* __restrict__ b1, const float* __restrict__ W2,
             const float* __restrict__ b2, float* __restrict__ out) {
    extern __shared__ __align__(1024) char smem[];
    const uint32_t sb = smem_u32(smem);
    const int tid  = threadIdx.x;
    const int lane = tid & 31;
    const int wid  = tid >> 5;
    const int m0 = blockIdx.x * BM;

    float* red_s = reinterpret_cast<float*>(smem + SM_RED);
    if (tid < BM) red_s[tid] = 0.0f;

    if (wid < 8) {
        // ================= CONSUMER =================
        const int warpN = wid;
        const uint32_t aInOff = (uint32_t)(((lane >> 3) & 1) * 8 + (lane & 7)) * 128;
        const uint32_t aXor   = ((uint32_t)(lane >> 4) * 16) ^ ((uint32_t)(lane & 7) << 4);
        const uint32_t bInOff = (uint32_t)(warpN * 64 + ((lane >> 4) & 1) * 8 + (lane & 7)) * 128;
        const uint32_t bXor   = (((uint32_t)(lane >> 3) & 1) * 16) ^ ((uint32_t)(lane & 7) << 4);

        float acc[4][8][4] = {};
        float rowsum[8] = {0.f, 0.f, 0.f, 0.f, 0.f, 0.f, 0.f, 0.f};
        uint32_t aa[2][4][4];
        uint32_t bb[2][8][2];

#define C_LOAD_FRAGS(kq, pb, bufA_, bufB_) do {                                       \
    const uint32_t kx_ = (uint32_t)((kq) << 5);                                       \
    _Pragma("unroll")                                                                 \
    for (int mt_ = 0; mt_ < 4; ++mt_)                                                 \
        LDSM_X4(aa[pb][mt_][0], aa[pb][mt_][1], aa[pb][mt_][2], aa[pb][mt_][3],       \
                (bufA_) + mt_ * 2048 + aInOff + (aXor ^ kx_));                        \
    _Pragma("unroll")                                                                 \
    for (int nt2_ = 0; nt2_ < 4; ++nt2_) {                                            \
        uint32_t r0_, r1_, r2_, r3_;                                                  \
        LDSM_X4(r0_, r1_, r2_, r3_, (bufB_) + bInOff + nt2_ * 2048 + (bXor ^ kx_));   \
        bb[pb][nt2_ * 2][0] = r0_;     bb[pb][nt2_ * 2][1] = r1_;                     \
        bb[pb][nt2_ * 2 + 1][0] = r2_; bb[pb][nt2_ * 2 + 1][1] = r3_;                 \
    }                                                                                 \
} while (0)

        __syncthreads();   // matches producer prologue fill

        for (int g = 0; g < TOTCHUNK; ++g) {
            const int p = g & 1;
            const uint32_t bufA = sb + SM_A0 + p * 8192;
            const uint32_t bufB = sb + SM_B  + p * 65536;

            C_LOAD_FRAGS(0, 0, bufA, bufB);
#pragma unroll
            for (int ks = 0; ks < 4; ++ks) {
                const int cur = ks & 1;
                if (ks < 3) C_LOAD_FRAGS(ks + 1, cur ^ 1, bufA, bufB);
#pragma unroll
                for (int mt = 0; mt < 4; ++mt)
#pragma unroll
                    for (int nt = 0; nt < 8; ++nt)
                        MMA16816(acc[mt][nt], aa[cur][mt], bb[cur][nt]);
            }

            if (g == NCHUNK - 1 || g == TOTCHUNK - 1) {
                const int w2o = (g >= NCHUNK) ? F_OUT : 0;
#pragma unroll
                for (int mt = 0; mt < 4; ++mt) {
#pragma unroll
                    for (int nt = 0; nt < 8; ++nt) {
                        const int nb = warpN * 64 + nt * 8 + (lane & 3) * 2;
                        const float2 bv = __ldg(reinterpret_cast<const float2*>(b1 + nb));
                        const float2 wv = __ldg(reinterpret_cast<const float2*>(W2 + w2o + nb));
                        float h;
                        h = fminf(fmaxf(acc[mt][nt][0] + bv.x, 0.f), 1.f); rowsum[mt*2+0] = fmaf(h, wv.x, rowsum[mt*2+0]);
                        h = fminf(fmaxf(acc[mt][nt][1] + bv.y, 0.f), 1.f); rowsum[mt*2+0] = fmaf(h, wv.y, rowsum[mt*2+0]);
                        h = fminf(fmaxf(acc[mt][nt][2] + bv.x, 0.f), 1.f); rowsum[mt*2+1] = fmaf(h, wv.x, rowsum[mt*2+1]);
                        h = fminf(fmaxf(acc[mt][nt][3] + bv.y, 0.f), 1.f); rowsum[mt*2+1] = fmaf(h, wv.y, rowsum[mt*2+1]);
                        acc[mt][nt][0] = 0.f; acc[mt][nt][1] = 0.f;
                        acc[mt][nt][2] = 0.f; acc[mt][nt][3] = 0.f;
                    }
                }
            }
            __syncthreads();   // chunk boundary (paired with producer)
        }

        // ---- reduce + sigmoid + store ----
#pragma unroll
        for (int r = 0; r < 8; ++r) {
            float v = rowsum[r];
            v += __shfl_xor_sync(0xFFFFFFFFu, v, 1);
            v += __shfl_xor_sync(0xFFFFFFFFu, v, 2);
            if ((lane & 3) == 0) {
                const int row = (r >> 1) * 16 + (r & 1) * 8 + (lane >> 2);
                atomicAdd(&red_s[row], v);
            }
        }
        __syncthreads();
        if (tid < BM) {
            const float z = red_s[tid] + __ldg(b2);
            out[m0 + tid] = 1.0f / (1.0f + expf(-z));
        }
    } else {
        // ================= PRODUCER (2 warps, 64 threads) =================
        const int pt = tid - 256;            // 0..63
        // A fill: thread -> row pt, FULL 64 f32 cols = 8 swizzled 16B stores
        const uint32_t aStsBase = (uint32_t)pt * 128;
        const uint32_t aRowXor  = ((uint32_t)(pt & 7)) << 4;
        // B fill: thread -> seg pt&7, rows (pt>>3) + 8*i  (i<64)
        const int bSeg  = pt & 7;
        const int bRow0 = pt >> 3;           // 0..7
        const uint32_t bDstBase = (uint32_t)bSeg * 16;

        // ---- prologue: fill buf0 with chunk 0 ----
        {
            const float4* s = reinterpret_cast<const float4*>(stm + (size_t)(m0 + pt) * F_IN);
#pragma unroll
            for (int j = 0; j < 8; ++j) {
                float4 v0 = s[2 * j], v1 = s[2 * j + 1];
                sts_a16(sb + SM_A0 + aStsBase + (((uint32_t)j * 16) ^ aRowXor), v0, v1);
            }
            const __half* bs = g_W1h + (size_t)bRow0 * F_IN + bSeg * 8;
#pragma unroll
            for (int i = 0; i < 64; ++i) {
                const int row = bRow0 + 8 * i;
                CP_ASYNC16(sb + SM_B + (uint32_t)row * 128 + (bDstBase ^ (((uint32_t)row & 7) << 4)),
                           bs + (size_t)(8 * i) * F_IN);
            }
            CP_COMMIT();
            CP_WAIT0();
        }
        __syncthreads();

        for (int g = 0; g < TOTCHUNK; ++g) {
            const int p = g & 1;
            if (g + 1 < TOTCHUNK) {
                const int g1 = g + 1;
                const float* X = (g1 >= NCHUNK) ? nstm : stm;
                const int c1 = g1 % NCHUNK;
                const uint32_t bufAn = sb + SM_A0 + (p ^ 1) * 8192;
                const uint32_t bufBn = sb + SM_B  + (p ^ 1) * 65536;
                // B via cp.async (issue first so it streams during A path)
                const __half* bs = g_W1h + (size_t)bRow0 * F_IN + c1 * BK + bSeg * 8;
#pragma unroll
                for (int i = 0; i < 64; ++i) {
                    const int row = bRow0 + 8 * i;
                    CP_ASYNC16(bufBn + (uint32_t)row * 128 + (bDstBase ^ (((uint32_t)row & 7) << 4)),
                               bs + (size_t)(8 * i) * F_IN);
                }
                CP_COMMIT();
                // A: LDG f32 -> cvt -> STS (full row: 8 x 16B)
                const float4* s = reinterpret_cast<const float4*>(
                    X + (size_t)(m0 + pt) * F_IN + c1 * BK);
#pragma unroll
                for (int j = 0; j < 8; ++j) {
                    float4 v0 = s[2 * j], v1 = s[2 * j + 1];
                    sts_a16(bufAn + aStsBase + (((uint32_t)j * 16) ^ aRowXor), v0, v1);
                }
                CP_WAIT0();
            }
            __syncthreads();   // chunk boundary (paired with consumer)
        }
        __syncthreads();       // pairs with consumers' post-reduce sync
    }
}

// ---------------- launch ----------------
extern "C" void kernel_launch(void* const* d_in, const int* in_sizes, int n_in,
                              void* d_out, int out_size) {
    const float* stm  = (const float*)d_in[0];
    const float* nstm = (const float*)d_in[1];
    const float* W1   = (const float*)d_in[2];
    const float* b1   = (const float*)d_in[3];
    const float* W2   = (const float*)d_in[4];
    const float* b2   = (const float*)d_in[5];
    float* out = (float*)d_out;

    cudaFuncSetAttribute(persp_kernel, cudaFuncAttributeMaxDynamicSharedMemorySize, SM_TOTAL);

    const int nconv = F_OUT * F_IN / 4;
    convert_w1_kernel<<<(nconv + 511) / 512, 512>>>(W1);
    persp_kernel<<<CTAS, NTHREADS, SM_TOTAL>>>(stm, nstm, b1, W2, b2, out);
}